// round 1
// baseline (speedup 1.0000x reference)
#include <cuda_runtime.h>
#include <cstdint>
#include <cstddef>

#define Bb   128
#define Tt   196
#define TT   392      // 2T
#define ENC  1024
#define DEC  512
#define Vv   98
#define Mm   294

// ---- scratch (no allocations allowed) ----
__device__ int            g_ids64;                 // 1 if masked_ids is int64
__device__ int            g_destTok[Bb * Vv];      // gemm row -> token index
__device__ unsigned char  g_vis[Bb * TT];          // 1 if (b,t) visible

// ============================================================
// Kernel 0: detect masked_ids element width (int32 vs int64).
// ids are unique in [0, 2T). If data is int32, an int64 view of
// the first row yields >=146 values >= 2^32; if int64, all < 392.
// ============================================================
__global__ void detect_kernel(const long long* __restrict__ p) {
    bool bad = false;
    for (int j = threadIdx.x; j < 147; j += blockDim.x) {
        long long v = p[j];
        if (v < 0 || v >= TT) bad = true;
    }
    bad = __syncthreads_or(bad);
    if (threadIdx.x == 0) g_ids64 = bad ? 0 : 1;
}

// ============================================================
// Kernel 1: per-row visible ids (ascending complement of masked)
// one block per batch row, 512 threads
// ============================================================
__global__ void __launch_bounds__(512)
visids_kernel(const void* __restrict__ mids_raw) {
    __shared__ unsigned char vis[TT];
    __shared__ int scan[512];
    const int b = blockIdx.x;
    const int t = threadIdx.x;
    const int ids64 = g_ids64;

    if (t < TT) vis[t] = 1;
    __syncthreads();

    if (ids64) {
        const long long* mids = (const long long*)mids_raw + (long long)b * Mm;
        for (int j = t; j < Mm; j += 512) vis[(int)mids[j]] = 0;
    } else {
        const int* mids = (const int*)mids_raw + b * Mm;
        for (int j = t; j < Mm; j += 512) vis[mids[j]] = 0;
    }
    __syncthreads();

    const int f = (t < TT) ? (int)vis[t] : 0;
    scan[t] = f;
    __syncthreads();
    #pragma unroll
    for (int off = 1; off < 512; off <<= 1) {
        int v = scan[t];
        int add = (t >= off) ? scan[t - off] : 0;
        __syncthreads();
        scan[t] = v + add;
        __syncthreads();
    }
    if (t < TT) {
        g_vis[b * TT + t] = (unsigned char)f;
        if (f) {
            int r = scan[t] - 1;     // rank among visible, ascending
            g_destTok[b * Vv + r] = t;
        }
    }
}

// ============================================================
// Kernel 2: fill masked rows with mask_token + pos + view
// (visible rows are fully overwritten by the GEMM epilogue)
// ============================================================
__global__ void __launch_bounds__(256)
fill_kernel(float4* __restrict__ out,
            const float4* __restrict__ mask_token,   // 128 float4
            const float4* __restrict__ pos,          // 392*128
            const float4* __restrict__ ve) {         // 2*128
    const int i = blockIdx.x * 256 + threadIdx.x;    // float4 index
    if (i >= Bb * TT * (DEC / 4)) return;
    const int d4  = i & 127;
    const int row = i >> 7;            // b*392 + t
    if (g_vis[row]) return;            // GEMM writes this row
    const int tok = row % TT;
    float4 mt = mask_token[d4];
    float4 pp = pos[tok * 128 + d4];
    float4 vv = ve[(tok >= Tt ? 128 : 0) + d4];
    out[i] = make_float4(mt.x + pp.x + vv.x, mt.y + pp.y + vv.y,
                         mt.z + pp.z + vv.z, mt.w + pp.w + vv.w);
}

// ============================================================
// Kernel 3: tf32 tensor-core GEMM + scatter epilogue
//   C[m,n] = sum_k x[m,k] * W[n,k];   m = b*98+v
//   out[b*392 + destTok[m], n] = C + bias + pos + view
// Block tile 128x64x16, 8 warps (4 M x 2 N), warp tile 32x32.
// ============================================================
#define BM 128
#define BN 64
#define BK 16
#define LDS_S 20   // smem row stride (words): conflict-free frag loads

__device__ __forceinline__ unsigned f2tf(float f) {
    unsigned u;
    asm("cvt.rna.tf32.f32 %0, %1;" : "=r"(u) : "f"(f));
    return u;
}

#define MMA_TF32(C, A, Bf)                                              \
    asm volatile(                                                       \
        "mma.sync.aligned.m16n8k8.row.col.f32.tf32.tf32.f32 "           \
        "{%0,%1,%2,%3}, {%4,%5,%6,%7}, {%8,%9}, {%0,%1,%2,%3};\n"       \
        : "+f"(C[0]), "+f"(C[1]), "+f"(C[2]), "+f"(C[3])                \
        : "r"(A[0]), "r"(A[1]), "r"(A[2]), "r"(A[3]),                   \
          "r"(Bf[0]), "r"(Bf[1]))

__global__ void __launch_bounds__(256, 2)
gemm_kernel(const float* __restrict__ x,     // [12544,1024]
            const float* __restrict__ W,     // [512,1024]
            const float* __restrict__ bias,  // [512]
            const float* __restrict__ pos,   // [392,512]
            const float* __restrict__ ve,    // [2,512]
            float* __restrict__ out) {       // [128,392,512]
    __shared__ __align__(16) unsigned As[2][BM * LDS_S];
    __shared__ __align__(16) unsigned Bs[2][BN * LDS_S];

    const int tid   = threadIdx.x;
    const int lane  = tid & 31;
    const int warp  = tid >> 5;
    const int warpM = warp & 3;          // 0..3
    const int warpN = warp >> 2;         // 0..1
    const int group = lane >> 2;         // 0..7
    const int tig   = lane & 3;          // 0..3
    const int m0 = blockIdx.x * BM;
    const int n0 = blockIdx.y * BN;

    // global-load mapping (per stage)
    const int arow = tid >> 2;           // 0..63 (second load: +64)
    const int akq  = (tid & 3) * 4;      // k offset within BK
    const int brow = tid >> 2;           // 0..63
    const int bkq  = (tid & 3) * 4;

    const float* xg = x + (size_t)m0 * ENC;
    const float* wg = W + (size_t)n0 * ENC;

    float c[2][4][4];
    #pragma unroll
    for (int i = 0; i < 2; i++)
        #pragma unroll
        for (int j = 0; j < 4; j++)
            #pragma unroll
            for (int k = 0; k < 4; k++) c[i][j][k] = 0.f;

    // prologue: load stage 0
    float4 pa0 = *(const float4*)(xg + (size_t)arow * ENC + akq);
    float4 pa1 = *(const float4*)(xg + (size_t)(arow + 64) * ENC + akq);
    float4 pb0 = *(const float4*)(wg + (size_t)brow * ENC + bkq);
    {
        uint4 u;
        u.x = f2tf(pa0.x); u.y = f2tf(pa0.y); u.z = f2tf(pa0.z); u.w = f2tf(pa0.w);
        *(uint4*)&As[0][arow * LDS_S + akq] = u;
        u.x = f2tf(pa1.x); u.y = f2tf(pa1.y); u.z = f2tf(pa1.z); u.w = f2tf(pa1.w);
        *(uint4*)&As[0][(arow + 64) * LDS_S + akq] = u;
        u.x = f2tf(pb0.x); u.y = f2tf(pb0.y); u.z = f2tf(pb0.z); u.w = f2tf(pb0.w);
        *(uint4*)&Bs[0][brow * LDS_S + bkq] = u;
    }
    __syncthreads();

    const int NKT = ENC / BK;            // 64
    #pragma unroll 1
    for (int kt = 0; kt < NKT; ++kt) {
        const int cur = kt & 1;
        if (kt + 1 < NKT) {
            const int ko = (kt + 1) * BK;
            pa0 = *(const float4*)(xg + (size_t)arow * ENC + ko + akq);
            pa1 = *(const float4*)(xg + (size_t)(arow + 64) * ENC + ko + akq);
            pb0 = *(const float4*)(wg + (size_t)brow * ENC + ko + bkq);
        }
        // compute current stage: 2 k8 steps
        #pragma unroll
        for (int ks = 0; ks < 2; ks++) {
            const int k8 = ks * 8;
            unsigned a[2][4], bf[4][2];
            #pragma unroll
            for (int mi = 0; mi < 2; mi++) {
                const int rb = warpM * 32 + mi * 16;
                a[mi][0] = As[cur][(rb + group)     * LDS_S + k8 + tig];
                a[mi][1] = As[cur][(rb + group + 8) * LDS_S + k8 + tig];
                a[mi][2] = As[cur][(rb + group)     * LDS_S + k8 + tig + 4];
                a[mi][3] = As[cur][(rb + group + 8) * LDS_S + k8 + tig + 4];
            }
            #pragma unroll
            for (int ni = 0; ni < 4; ni++) {
                const int nb = warpN * 32 + ni * 8;
                bf[ni][0] = Bs[cur][(nb + group) * LDS_S + k8 + tig];
                bf[ni][1] = Bs[cur][(nb + group) * LDS_S + k8 + tig + 4];
            }
            #pragma unroll
            for (int mi = 0; mi < 2; mi++)
                #pragma unroll
                for (int ni = 0; ni < 4; ni++)
                    MMA_TF32(c[mi][ni], a[mi], bf[ni]);
        }
        if (kt + 1 < NKT) {
            const int nxt = cur ^ 1;
            uint4 u;
            u.x = f2tf(pa0.x); u.y = f2tf(pa0.y); u.z = f2tf(pa0.z); u.w = f2tf(pa0.w);
            *(uint4*)&As[nxt][arow * LDS_S + akq] = u;
            u.x = f2tf(pa1.x); u.y = f2tf(pa1.y); u.z = f2tf(pa1.z); u.w = f2tf(pa1.w);
            *(uint4*)&As[nxt][(arow + 64) * LDS_S + akq] = u;
            u.x = f2tf(pb0.x); u.y = f2tf(pb0.y); u.z = f2tf(pb0.z); u.w = f2tf(pb0.w);
            *(uint4*)&Bs[nxt][brow * LDS_S + bkq] = u;
        }
        __syncthreads();
    }

    // epilogue: scatter rows to out[b*392 + tok] with bias+pos+view fused
    const int m_base = m0 + warpM * 32;
    const int n_base = n0 + warpN * 32;
    #pragma unroll
    for (int mi = 0; mi < 2; mi++) {
        #pragma unroll
        for (int rs = 0; rs < 2; rs++) {
            const int m   = m_base + mi * 16 + group + rs * 8;
            const int bb  = m / Vv;
            const int tok = g_destTok[m];
            const float* prow = pos + tok * DEC;
            const float* vrow = ve + (tok >= Tt ? DEC : 0);
            float* optr = out + ((size_t)bb * TT + tok) * DEC;
            #pragma unroll
            for (int ni = 0; ni < 4; ni++) {
                const int n = n_base + ni * 8 + 2 * tig;
                float2 bp = *(const float2*)(bias + n);
                float2 pp = *(const float2*)(prow + n);
                float2 vv = *(const float2*)(vrow + n);
                float2 r;
                r.x = c[mi][ni][rs * 2 + 0] + bp.x + pp.x + vv.x;
                r.y = c[mi][ni][rs * 2 + 1] + bp.y + pp.y + vv.y;
                *(float2*)(optr + n) = r;
            }
        }
    }
}

// ============================================================
// launch
// ============================================================
extern "C" void kernel_launch(void* const* d_in, const int* in_sizes, int n_in,
                              void* d_out, int out_size) {
    const float* x          = (const float*)d_in[0];
    const void*  masked_ids = d_in[1];
    const float* W          = (const float*)d_in[2];
    const float* bias       = (const float*)d_in[3];
    const float* mask_token = (const float*)d_in[4];
    const float* pos        = (const float*)d_in[5];
    const float* ve         = (const float*)d_in[6];
    float* out = (float*)d_out;

    detect_kernel<<<1, 256>>>((const long long*)masked_ids);
    visids_kernel<<<Bb, 512>>>(masked_ids);

    const int tot4 = Bb * TT * (DEC / 4);
    fill_kernel<<<(tot4 + 255) / 256, 256>>>(
        (float4*)out, (const float4*)mask_token, (const float4*)pos,
        (const float4*)ve);

    dim3 grid(Bb * Vv / BM, DEC / BN);   // (98, 8)
    gemm_kernel<<<grid, 256>>>(x, W, bias, pos, ve, out);
}

// round 4
// speedup vs baseline: 1.7254x; 1.7254x over previous
#include <cuda_runtime.h>
#include <cstdint>
#include <cstddef>

#define Bb   128
#define Tt   196
#define TT   392      // 2T
#define ENC  1024
#define DEC  512
#define Vv   98
#define Mm   294

// ---- scratch (no allocations allowed) ----
__device__ int            g_destTok[Bb * Vv];      // gemm row -> token index
__device__ unsigned char  g_vis[Bb * TT];          // 1 if (b,t) visible

__device__ __forceinline__ uint32_t s2u(const void* p) {
    uint32_t a;
    asm("{ .reg .u64 t; cvta.to.shared.u64 t, %1; cvt.u32.u64 %0, t; }"
        : "=r"(a) : "l"(p));
    return a;
}

#define LDSM_X4(r, addr)                                                       \
    asm volatile("ldmatrix.sync.aligned.m8n8.x4.shared.b16 {%0,%1,%2,%3}, [%4];"\
        : "=r"((r)[0]), "=r"((r)[1]), "=r"((r)[2]), "=r"((r)[3]) : "r"(addr))

#define MMA_TF32(C, A, Bf)                                                     \
    asm volatile(                                                              \
        "mma.sync.aligned.m16n8k8.row.col.f32.tf32.tf32.f32 "                  \
        "{%0,%1,%2,%3}, {%4,%5,%6,%7}, {%8,%9}, {%0,%1,%2,%3};\n"              \
        : "+f"((C)[0]), "+f"((C)[1]), "+f"((C)[2]), "+f"((C)[3])               \
        : "r"((A)[0]), "r"((A)[1]), "r"((A)[2]), "r"((A)[3]),                  \
          "r"((Bf)[0]), "r"((Bf)[1]))

// ============================================================
// Kernel 1: per-row visible ids (ascending complement).
// masked_ids dtype (int32/int64) detected inline from row 0.
// ============================================================
__global__ void __launch_bounds__(512)
visids_kernel(const void* __restrict__ mids_raw) {
    __shared__ unsigned char vis[TT];
    __shared__ int scan[512];
    const int b = blockIdx.x;
    const int t = threadIdx.x;

    bool bad = false;
    {
        const long long* p = (const long long*)mids_raw;
        for (int j = t; j < 147; j += 512) {
            long long v = p[j];
            if (v < 0 || v >= TT) bad = true;
        }
    }
    const int ids64 = __syncthreads_or(bad) ? 0 : 1;

    if (t < TT) vis[t] = 1;
    __syncthreads();
    if (ids64) {
        const long long* mids = (const long long*)mids_raw + (long long)b * Mm;
        for (int j = t; j < Mm; j += 512) vis[(int)mids[j]] = 0;
    } else {
        const int* mids = (const int*)mids_raw + b * Mm;
        for (int j = t; j < Mm; j += 512) vis[mids[j]] = 0;
    }
    __syncthreads();

    const int f = (t < TT) ? (int)vis[t] : 0;
    scan[t] = f;
    __syncthreads();
    #pragma unroll
    for (int off = 1; off < 512; off <<= 1) {
        int v = scan[t];
        int add = (t >= off) ? scan[t - off] : 0;
        __syncthreads();
        scan[t] = v + add;
        __syncthreads();
    }
    if (t < TT) {
        g_vis[b * TT + t] = (unsigned char)f;
        if (f) g_destTok[b * Vv + (scan[t] - 1)] = t;
    }
}

// ============================================================
// Kernel 2 (fused): tf32 mma.sync GEMM (CTAs 0..391) + fill (392..441)
//   GEMM: BM=128 BN=128 BK=32, cp.async 3-stage, ldmatrix.x4 frags,
//         raw-fp32-as-tf32 (no cvt), fused scatter epilogue.
// ============================================================
#define GEMMB   392                    // 98 m-blocks x 4 n-blocks
#define FILLB   50
#define BM      128
#define BN      128
#define BK      32
#define NCHUNK  (ENC / BK)             // 32
#define A_BYTES (BM * BK * 4)          // 16 KB
#define B_BYTES (BN * BK * 4)          // 16 KB
#define STAGE   (A_BYTES + B_BYTES)    // 32 KB
#define NSTAGE  3
#define SMEM_DYN (NSTAGE * STAGE)      // 96 KB

__device__ __forceinline__ void load_stage(uint32_t smem_base, int s, int kt,
                                           const float* __restrict__ x,
                                           const float* __restrict__ W,
                                           int m0, int n0, int tid) {
    const uint32_t abase = smem_base + s * STAGE;
    const uint32_t bbase = abase + A_BYTES;
    const float* xs = x + (size_t)m0 * ENC + kt * BK;
    const float* ws = W + (size_t)n0 * ENC + kt * BK;
    // A: 128 rows x 8 chunks = 1024 chunks; B same. 8 cp.async / thread.
    #pragma unroll
    for (int i = 0; i < 4; i++) {
        int c = tid + i * 256;
        int r = c >> 3, u = c & 7;
        uint32_t dst = abase + r * 128 + ((u ^ (r & 7)) << 4);
        const float* src = xs + (size_t)r * ENC + u * 4;
        asm volatile("cp.async.cg.shared.global [%0], [%1], 16;"
                     :: "r"(dst), "l"(src));
    }
    #pragma unroll
    for (int i = 0; i < 4; i++) {
        int c = tid + i * 256;
        int r = c >> 3, u = c & 7;
        uint32_t dst = bbase + r * 128 + ((u ^ (r & 7)) << 4);
        const float* src = ws + (size_t)r * ENC + u * 4;
        asm volatile("cp.async.cg.shared.global [%0], [%1], 16;"
                     :: "r"(dst), "l"(src));
    }
    asm volatile("cp.async.commit_group;" ::: "memory");
}

__global__ void __launch_bounds__(256, 2)
fused_kernel(const float* __restrict__ x,          // [12544,1024]
             const float* __restrict__ W,          // [512,1024]
             const float* __restrict__ bias,       // [512]
             const float* __restrict__ mask_token, // [512]
             const float* __restrict__ pos,        // [392,512]
             const float* __restrict__ ve,         // [2,512]
             float* __restrict__ out) {            // [128,392,512]
    const int tid  = threadIdx.x;
    const int wid  = tid >> 5;
    const int lane = tid & 31;

    if (blockIdx.x >= GEMMB) {
        // ---------------- fill path ----------------
        const int wg = (blockIdx.x - GEMMB) * 8 + wid;   // 0..399
        float4 mt[4], ves[2][4];
        const float4* mt4  = (const float4*)mask_token;
        const float4* ve4  = (const float4*)ve;
        const float4* pos4 = (const float4*)pos;
        float4* out4 = (float4*)out;
        #pragma unroll
        for (int j = 0; j < 4; j++) {
            mt[j]     = mt4[lane + 32 * j];
            ves[0][j] = ve4[lane + 32 * j];
            ves[1][j] = ve4[128 + lane + 32 * j];
        }
        for (int row = wg; row < Bb * TT; row += FILLB * 8) {
            if (g_vis[row]) continue;
            const int tok = row % TT;
            const int vs  = (tok >= Tt) ? 1 : 0;
            const float4* prow = pos4 + tok * 128;
            float4* orow = out4 + (size_t)row * 128;
            #pragma unroll
            for (int j = 0; j < 4; j++) {
                const int d4 = lane + 32 * j;
                float4 pp = prow[d4];
                float4 o;
                o.x = mt[j].x + pp.x + ves[vs][j].x;
                o.y = mt[j].y + pp.y + ves[vs][j].y;
                o.z = mt[j].z + pp.z + ves[vs][j].z;
                o.w = mt[j].w + pp.w + ves[vs][j].w;
                orow[d4] = o;
            }
        }
        return;
    }

    // ---------------- GEMM path ----------------
    extern __shared__ __align__(1024) char smem[];
    const uint32_t smem_base = s2u(smem);

    const int mblk = blockIdx.x >> 2;
    const int nblk = blockIdx.x & 3;
    const int m0 = mblk * BM;
    const int n0 = nblk * BN;
    const int warpM = wid & 3;           // 4 warps over M (32 rows each)
    const int warpN = wid >> 2;          // 2 warps over N (64 cols each)

    // ldmatrix per-thread address components
    // A: block = lane/8; row = warpM*32 + mt*16 + ((lane>>3)&1)*8 + (lane&7)
    //    chunk-half = lane>>4
    const int aRow0 = warpM * 32 + ((lane >> 3) & 1) * 8 + (lane & 7);
    const int aChalf = lane >> 4;
    uint32_t aOff[2];
    int aRx[2];
    #pragma unroll
    for (int mt = 0; mt < 2; mt++) {
        int r = aRow0 + mt * 16;
        aOff[mt] = (uint32_t)(r * 128);
        aRx[mt]  = r & 7;
    }
    // B: ntile-pair per x4: row = warpN*64 + j*16 + (lane>>4)*8 + (lane&7)
    //    chunk-half = (lane>>3)&1
    const int bRow0 = warpN * 64 + (lane >> 4) * 8 + (lane & 7);
    const int bChalf = (lane >> 3) & 1;
    uint32_t bOff[4];
    int bRx[4];
    #pragma unroll
    for (int j = 0; j < 4; j++) {
        int r = bRow0 + j * 16;
        bOff[j] = (uint32_t)(r * 128);
        bRx[j]  = r & 7;
    }

    float c[2][8][4];
    #pragma unroll
    for (int i = 0; i < 2; i++)
        #pragma unroll
        for (int j = 0; j < 8; j++)
            #pragma unroll
            for (int k = 0; k < 4; k++) c[i][j][k] = 0.f;

    load_stage(smem_base, 0, 0, x, W, m0, n0, tid);
    load_stage(smem_base, 1, 1, x, W, m0, n0, tid);

    #pragma unroll 1
    for (int kt = 0; kt < NCHUNK; ++kt) {
        if (kt + 2 < NCHUNK) {
            load_stage(smem_base, (kt + 2) % NSTAGE, kt + 2, x, W, m0, n0, tid);
            asm volatile("cp.async.wait_group 2;" ::: "memory");
        } else if (kt + 1 < NCHUNK) {
            asm volatile("cp.async.wait_group 1;" ::: "memory");
        } else {
            asm volatile("cp.async.wait_group 0;" ::: "memory");
        }
        __syncthreads();

        const uint32_t Ab = smem_base + (kt % NSTAGE) * STAGE;
        const uint32_t Bbs = Ab + A_BYTES;
        #pragma unroll
        for (int ks = 0; ks < 4; ks++) {
            unsigned a[2][4], b[8][2];
            #pragma unroll
            for (int mt = 0; mt < 2; mt++) {
                uint32_t ad = Ab + aOff[mt] +
                              (uint32_t)(((2 * ks + aChalf) ^ aRx[mt]) << 4);
                LDSM_X4(a[mt], ad);
            }
            #pragma unroll
            for (int j = 0; j < 4; j++) {
                uint32_t bd = Bbs + bOff[j] +
                              (uint32_t)(((2 * ks + bChalf) ^ bRx[j]) << 4);
                LDSM_X4((&b[2 * j][0]), bd);   // fills b[2j][0..1], b[2j+1][0..1]
            }
            #pragma unroll
            for (int mt = 0; mt < 2; mt++)
                #pragma unroll
                for (int ni = 0; ni < 8; ni++)
                    MMA_TF32(c[mt][ni], a[mt], b[ni]);
        }
        __syncthreads();
    }

    // epilogue: scatter with bias + pos + view fused
    const int group = lane >> 2;
    const int tig   = lane & 3;
    const int m_base = m0 + warpM * 32;
    const int n_base = n0 + warpN * 64;
    #pragma unroll
    for (int mt = 0; mt < 2; mt++) {
        #pragma unroll
        for (int rs = 0; rs < 2; rs++) {
            const int m   = m_base + mt * 16 + rs * 8 + group;
            const int bb  = m / Vv;
            const int tok = g_destTok[m];
            const float* prow = pos + tok * DEC;
            const float* vrow = ve + (tok >= Tt ? DEC : 0);
            float* optr = out + ((size_t)bb * TT + tok) * DEC;
            #pragma unroll
            for (int ni = 0; ni < 8; ni++) {
                const int n = n_base + ni * 8 + 2 * tig;
                float2 bp = *(const float2*)(bias + n);
                float2 pp = *(const float2*)(prow + n);
                float2 vv = *(const float2*)(vrow + n);
                float2 r;
                r.x = c[mt][ni][rs * 2 + 0] + bp.x + pp.x + vv.x;
                r.y = c[mt][ni][rs * 2 + 1] + bp.y + pp.y + vv.y;
                *(float2*)(optr + n) = r;
            }
        }
    }
}

// ============================================================
// launch
// ============================================================
extern "C" void kernel_launch(void* const* d_in, const int* in_sizes, int n_in,
                              void* d_out, int out_size) {
    const float* x          = (const float*)d_in[0];
    const void*  masked_ids = d_in[1];
    const float* W          = (const float*)d_in[2];
    const float* bias       = (const float*)d_in[3];
    const float* mask_token = (const float*)d_in[4];
    const float* pos        = (const float*)d_in[5];
    const float* ve         = (const float*)d_in[6];
    float* out = (float*)d_out;

    cudaFuncSetAttribute(fused_kernel,
                         cudaFuncAttributeMaxDynamicSharedMemorySize, SMEM_DYN);

    visids_kernel<<<Bb, 512>>>(masked_ids);
    fused_kernel<<<GEMMB + FILLB, 256, SMEM_DYN>>>(
        x, W, bias, mask_token, pos, ve, out);
}